// round 15
// baseline (speedup 1.0000x reference)
#include <cuda_runtime.h>
#include <cstddef>

#define BATCH   8
#define T_LEN   4096
#define HC      256
#define HD      512
#define NROWS   (BATCH * T_LEN)
#define PD      4

// dynamic smem layout (bytes)
#define SM_MBAR   0
#define SM_STAGE  16
#define SM_HBUF   272                  // 2 x 512 f
#define SM_RING   4368                 // 8 x 64 f   (L1)
#define SM_HHIST  6416                 // 16 x 512 f (L0)
#define SM_WS     39184                // 64 x 516 f (L0)
#define WS_PITCH  516
#define SMEM_TOTAL (SM_WS + 64 * WS_PITCH * 4)   // 171280

__device__ float g_wx [NROWS * HD];    // layer-0 input projection
__device__ float g_wx1[NROWS * HD];    // W1*h0 + b1 (L0 bursts)
__device__ unsigned g_flags[64];       // wx1 16-block progress per (b,rank)

#define FMA2(a, x, y) asm("fma.rn.f32x2 %0, %1, %2, %0;" : "+l"(a) : "l"(x), "l"(y))

static __device__ __forceinline__ unsigned su32(const void* p) {
    return (unsigned)__cvta_generic_to_shared(p);
}
static __device__ __forceinline__ unsigned long long packf2(float lo, float hi) {
    unsigned long long r;
    asm("mov.b64 %0, {%1, %2};" : "=l"(r) : "f"(lo), "f"(hi));
    return r;
}
static __device__ __forceinline__ void unpackf2(unsigned long long v, float& lo, float& hi) {
    asm("mov.b64 {%0, %1}, %2;" : "=f"(lo), "=f"(hi) : "l"(v));
}
static __device__ __forceinline__ float hw_tanh(float x) {
    float y; asm("tanh.approx.f32 %0, %1;" : "=f"(y) : "f"(x)); return y;
}
static __device__ __forceinline__ void mbar_wait(unsigned a, unsigned p) {
    asm volatile(
        "{\n\t.reg .pred P;\nLW_%=:\n\t"
        "mbarrier.try_wait.parity.acquire.cluster.shared::cta.b64 P, [%0], %1, 0x989680;\n\t"
        "@P bra LD_%=;\n\tbra LW_%=;\nLD_%=:\n\t}"
        :: "r"(a), "r"(p) : "memory");
}
static __device__ __forceinline__ unsigned ld_acq(const unsigned* p) {
    unsigned v;
    asm volatile("ld.acquire.gpu.global.u32 %0, [%1];" : "=r"(v) : "l"(p) : "memory");
    return v;
}
static __device__ __forceinline__ void st_rel(unsigned* p, unsigned v) {
    asm volatile("st.release.gpu.global.u32 [%0], %1;" :: "l"(p), "r"(v) : "memory");
}
static __device__ __forceinline__ void cp16(unsigned d, const void* s) {
    asm volatile("cp.async.cg.shared.global [%0], [%1], 16;" :: "r"(d), "l"(s) : "memory");
}
static __device__ __forceinline__ void bulk_send(unsigned dst, unsigned src, unsigned mb) {
    asm volatile("fence.proxy.async.shared::cta;" ::: "memory");
    asm volatile(
        "cp.async.bulk.shared::cluster.shared::cta.mbarrier::complete_tx::bytes [%0], [%1], %2, [%3];"
        :: "r"(dst), "r"(src), "r"(256u), "r"(mb) : "memory");
}
static __device__ __forceinline__ void rearm(unsigned mb) {
    asm volatile("mbarrier.arrive.expect_tx.shared::cta.b64 _, [%0], %1;"
                 :: "r"(mb), "r"(2048u) : "memory");
}

// U-slice -> registers (R9 layout)
static __device__ void load_u(unsigned long long w2[4][16], int kg, int jj, bool jhi,
                              const float* ur, const float* ui)
{
#pragma unroll
    for (int q = 0; q < 8; ++q) {
        const int k = q * 64 + kg * 4;
        float4 r0, r1, r2, r3;
        if (k < 256) {
            const float* s = (jhi ? ui : ur) + (size_t)k * 256 + jj;
            r0 = *(const float4*)(s);       r1 = *(const float4*)(s + 256);
            r2 = *(const float4*)(s + 512); r3 = *(const float4*)(s + 768);
        } else {
            const float* s = (jhi ? ur : ui) + (size_t)(k - 256) * 256 + jj;
            const float g = jhi ? 1.f : -1.f;
            r0 = *(const float4*)(s);       r1 = *(const float4*)(s + 256);
            r2 = *(const float4*)(s + 512); r3 = *(const float4*)(s + 768);
            r0.x*=g; r0.y*=g; r0.z*=g; r0.w*=g; r1.x*=g; r1.y*=g; r1.z*=g; r1.w*=g;
            r2.x*=g; r2.y*=g; r2.z*=g; r2.w*=g; r3.x*=g; r3.y*=g; r3.z*=g; r3.w*=g;
        }
        w2[0][2*q] = packf2(r0.x, r1.x); w2[1][2*q] = packf2(r0.y, r1.y);
        w2[2][2*q] = packf2(r0.z, r1.z); w2[3][2*q] = packf2(r0.w, r1.w);
        w2[0][2*q+1] = packf2(r2.x, r3.x); w2[1][2*q+1] = packf2(r2.y, r3.y);
        w2[2][2*q+1] = packf2(r2.z, r3.z); w2[3][2*q+1] = packf2(r2.w, r3.w);
    }
}

// 16-step W1 burst: wx1[s0..s0+15][rank*64+jb] from hhist
static __device__ void burst_w1(const float* Ws, const float* hhist,
                                float* dst0, int jb, int ko, float wb1j)
{
    unsigned long long acc[16];
#pragma unroll
    for (int tt = 0; tt < 16; ++tt) acc[tt] = 0;
#pragma unroll 4
    for (int m = 0; m < 32; ++m) {
        const int k4 = m * 16 + ko * 4;
        ulonglong2 wv = *(const ulonglong2*)(Ws + (size_t)jb * WS_PITCH + k4);
#pragma unroll
        for (int tt = 0; tt < 16; ++tt) {
            ulonglong2 hv = *(const ulonglong2*)(hhist + (size_t)tt * HD + k4);
            FMA2(acc[tt], hv.x, wv.x);
            FMA2(acc[tt], hv.y, wv.y);
        }
    }
#pragma unroll
    for (int tt = 0; tt < 16; ++tt) {
        float lo, hi; unpackf2(acc[tt], lo, hi);
        float s = lo + hi;
        s += __shfl_xor_sync(0xffffffffu, s, 1);
        s += __shfl_xor_sync(0xffffffffu, s, 2);
        if (ko == 0) dst0[(size_t)tt * HD] = s + wb1j;
    }
}

// ---------------------------------------------------------------------------
__global__ __launch_bounds__(256) void proj_kernel(
    const float* __restrict__ X,
    const float* __restrict__ wr, const float* __restrict__ wi,
    const float* __restrict__ br, const float* __restrict__ bi,
    float* __restrict__ Y)
{
    __shared__ float As[16][132];
    __shared__ float Bs[16][132];
    const int bm = blockIdx.x * 128, bn = blockIdx.y * 128, tid = threadIdx.x;
    const int tx = tid & 15, ty = tid >> 4, am = tid >> 1, ak = (tid & 1) * 8;
    const int bk = tid >> 4, bj = (tid & 15) * 8;
    const bool jhi = (bn + bj) >= 256;
    const int  jj  = (bn + bj) & 255;

    float acc[8][8];
#pragma unroll
    for (int r = 0; r < 8; ++r)
#pragma unroll
        for (int c = 0; c < 8; ++c) acc[r][c] = 0.f;

    for (int k0 = 0; k0 < HD; k0 += 16) {
        const float* xrow = X + (size_t)(bm + am) * HD + k0 + ak;
        float4 a0 = *(const float4*)(xrow), a1 = *(const float4*)(xrow + 4);
        As[ak+0][am]=a0.x; As[ak+1][am]=a0.y; As[ak+2][am]=a0.z; As[ak+3][am]=a0.w;
        As[ak+4][am]=a1.x; As[ak+5][am]=a1.y; As[ak+6][am]=a1.z; As[ak+7][am]=a1.w;
        {
            int k = k0 + bk;
            float4 b0, b1;
            if (k < 256) {
                const float* s = (jhi ? wi : wr) + (size_t)k * 256 + jj;
                b0 = *(const float4*)(s); b1 = *(const float4*)(s + 4);
            } else {
                const float* s = (jhi ? wr : wi) + (size_t)(k - 256) * 256 + jj;
                b0 = *(const float4*)(s); b1 = *(const float4*)(s + 4);
                if (!jhi) {
                    b0.x=-b0.x; b0.y=-b0.y; b0.z=-b0.z; b0.w=-b0.w;
                    b1.x=-b1.x; b1.y=-b1.y; b1.z=-b1.z; b1.w=-b1.w;
                }
            }
            *(float4*)&Bs[bk][bj] = b0; *(float4*)&Bs[bk][bj+4] = b1;
        }
        __syncthreads();
#pragma unroll
        for (int kk = 0; kk < 16; ++kk) {
            float4 av0 = *(const float4*)&As[kk][ty*8], av1 = *(const float4*)&As[kk][ty*8+4];
            float4 bv0 = *(const float4*)&Bs[kk][tx*8], bv1 = *(const float4*)&Bs[kk][tx*8+4];
            float a[8] = {av0.x,av0.y,av0.z,av0.w,av1.x,av1.y,av1.z,av1.w};
            float b[8] = {bv0.x,bv0.y,bv0.z,bv0.w,bv1.x,bv1.y,bv1.z,bv1.w};
#pragma unroll
            for (int r = 0; r < 8; ++r)
#pragma unroll
                for (int c = 0; c < 8; ++c) acc[r][c] = fmaf(a[r], b[c], acc[r][c]);
        }
        __syncthreads();
    }
    const int col0 = bn + tx * 8;
    float bias[8];
#pragma unroll
    for (int c = 0; c < 8; ++c) { int j = col0 + c; bias[c] = (j<256)?br[j]:bi[j-256]; }
#pragma unroll
    for (int r = 0; r < 8; ++r) {
        float* y = Y + (size_t)(bm + ty*8 + r) * HD + col0;
        *(float4*)(y)   = make_float4(acc[r][0]+bias[0],acc[r][1]+bias[1],acc[r][2]+bias[2],acc[r][3]+bias[3]);
        *(float4*)(y+4) = make_float4(acc[r][4]+bias[4],acc[r][5]+bias[5],acc[r][6]+bias[6],acc[r][7]+bias[7]);
    }
}

// ---------------------------------------------------------------------------
// L0: R9 scan + h history + 16-step W1 bursts -> wx1 + flags. No h0 STG.
// ---------------------------------------------------------------------------
static __device__ void scan_l0(
    char* dsm, unsigned rank, int b, const float* __restrict__ wx,
    const float* ur, const float* ui, const float* ubr, const float* ubi,
    const float* w1r, const float* w1i, const float* w1br, const float* w1bi,
    float* __restrict__ wx1, unsigned* flags)
{
    float* hbuf  = (float*)(dsm + SM_HBUF);
    float* stage = (float*)(dsm + SM_STAGE);
    float* hhist = (float*)(dsm + SM_HHIST);
    float* Ws    = (float*)(dsm + SM_WS);
    const unsigned hb = su32(hbuf), st = su32(stage), mb = su32(dsm + SM_MBAR);

    const int tid = threadIdx.x, lane = tid & 31;
    const int jg = tid >> 4, kg = tid & 15;
    const int j0 = (int)rank * 64 + jg * 4, jj = j0 & 255;
    const bool jhi = j0 >= 256;
    const int  jb0 = ((int)rank * 64) & 255;
    const bool chi = ((int)rank * 64) >= 256;

    unsigned dsth, dstm;
    { const int d = tid & 7;
      asm("mapa.shared::cluster.u32 %0, %1, %2;" : "=r"(dsth) : "r"(hb), "r"(d));
      asm("mapa.shared::cluster.u32 %0, %1, %2;" : "=r"(dstm) : "r"(mb), "r"(d)); }
    const unsigned dslot = dsth + (unsigned)(rank * 256);

    unsigned long long w2[4][16];
    load_u(w2, kg, jj, jhi, ur, ui);
    const float4 ub = jhi ? *(const float4*)(ubi + jj) : *(const float4*)(ubr + jj);

    // W1 slice -> SMEM Ws[j][k]
    for (int it = tid; it < 512 * 16; it += 256) {
        const int k = it >> 4, j4 = (it & 15) * 4;
        float4 v; float g;
        if (k < 256) { v = *(const float4*)((chi ? w1i : w1r) + (size_t)k*256 + jb0 + j4); g = 1.f; }
        else { v = *(const float4*)((chi ? w1r : w1i) + (size_t)(k-256)*256 + jb0 + j4); g = chi ? 1.f : -1.f; }
        Ws[(j4+0)*WS_PITCH + k] = v.x*g; Ws[(j4+1)*WS_PITCH + k] = v.y*g;
        Ws[(j4+2)*WS_PITCH + k] = v.z*g; Ws[(j4+3)*WS_PITCH + k] = v.w*g;
    }
    const int jb = tid >> 2, ko = tid & 3;
    const float wb1j = (chi ? w1bi : w1br)[jb0 + jb];

    const float* wx_b = wx + (size_t)b * (T_LEN * HD);
    float* wx1_b = wx1 + (size_t)b * (T_LEN * HD);
    float* bdst  = wx1_b + rank * 64 + jb;
    unsigned* my_flag = flags + b * 8 + rank;
    const bool sl = ((lane & 15) == 0);
    const bool hw = (tid >= 32 && tid < 48);

    __syncthreads();   // Ws ready

    // t = 0
    {
        float4 wv = *(const float4*)(wx_b + j0);
        if (sl) {
            float4 y;
            y.x = hw_tanh(wv.x + ub.x); y.y = hw_tanh(wv.y + ub.y);
            y.z = hw_tanh(wv.z + ub.z); y.w = hw_tanh(wv.w + ub.w);
            *(float4*)&stage[jg * 4] = y;
        }
        __syncthreads();
        if (tid < 8) bulk_send(dslot, st, dstm);
    }

    for (int t = 1; t < T_LEN; ++t) {
        float4 wv = *(const float4*)(wx_b + (size_t)t * HD + j0);
        wv.x += ub.x; wv.y += ub.y; wv.z += ub.z; wv.w += ub.w;

        const int use = t - 1, rbuf = use & 1;
        mbar_wait(mb + rbuf * 8, (unsigned)((use >> 1) & 1));
        if (tid == 0) rearm(mb + rbuf * 8);

        unsigned long long h2[16];
        const float* hp = hbuf + rbuf * HD;
#pragma unroll
        for (int q = 0; q < 8; ++q) {
            ulonglong2 v = *(const ulonglong2*)(hp + q * 64 + kg * 4);
            h2[2*q] = v.x; h2[2*q+1] = v.y;
        }
        if (hw) {   // archive h(t-1)
            float* hd = hhist + (size_t)(use & 15) * HD;
#pragma unroll
            for (int q = 0; q < 8; ++q) {
                ulonglong2 v; v.x = h2[2*q]; v.y = h2[2*q+1];
                *(ulonglong2*)(hd + q * 64 + kg * 4) = v;
            }
        }

        unsigned long long a0 = 0, a1 = 0, a2 = 0, a3 = 0;
#pragma unroll
        for (int q = 0; q < 16; ++q) {
            FMA2(a0, h2[q], w2[0][q]); FMA2(a1, h2[q], w2[1][q]);
            FMA2(a2, h2[q], w2[2][q]); FMA2(a3, h2[q], w2[3][q]);
        }
        float s0, s1, s2, s3, hq;
        unpackf2(a0, s0, hq); s0 += hq; unpackf2(a1, s1, hq); s1 += hq;
        unpackf2(a2, s2, hq); s2 += hq; unpackf2(a3, s3, hq); s3 += hq;
#pragma unroll
        for (int off = 1; off < 16; off <<= 1) {
            s0 += __shfl_xor_sync(0xffffffffu, s0, off);
            s1 += __shfl_xor_sync(0xffffffffu, s1, off);
            s2 += __shfl_xor_sync(0xffffffffu, s2, off);
            s3 += __shfl_xor_sync(0xffffffffu, s3, off);
        }
        if (sl) {
            float4 y;
            y.x = hw_tanh(wv.x + s0); y.y = hw_tanh(wv.y + s1);
            y.z = hw_tanh(wv.z + s2); y.w = hw_tanh(wv.w + s3);
            *(float4*)&stage[jg * 4] = y;
        }
        __syncthreads();
        if (tid < 8)
            bulk_send(dslot + (unsigned)((t & 1) * 2048), st, dstm + (unsigned)((t & 1) * 8));

        if ((t & 15) == 0) {   // burst: block t/16 = steps [t-16, t)
            burst_w1(Ws, hhist, bdst + (size_t)(t - 16) * HD, jb, ko, wb1j);
            __syncthreads();
            if (tid == 0) st_rel(my_flag, (unsigned)(t >> 4));
        }
    }

    // final phase: archive h(4095), last burst, final flag
    mbar_wait(mb + ((T_LEN - 1) & 1) * 8, (unsigned)(((T_LEN - 1) >> 1) & 1));
    if (hw) {
        const float* hp = hbuf + ((T_LEN - 1) & 1) * HD;
        float* hd = hhist + 15 * HD;
#pragma unroll
        for (int q = 0; q < 8; ++q)
            *(ulonglong2*)(hd + q * 64 + kg * 4) =
                *(const ulonglong2*)(hp + q * 64 + kg * 4);
    }
    __syncthreads();
    burst_w1(Ws, hhist, bdst + (size_t)(T_LEN - 16) * HD, jb, ko, wb1j);
    __syncthreads();
    if (tid == 0) st_rel(my_flag, 256u);
}

// ---------------------------------------------------------------------------
// L1: R12 ring scan over wx1, gated per 16-block.
// ---------------------------------------------------------------------------
static __device__ void scan_l1(
    char* dsm, unsigned rank, int b, const float* __restrict__ wx,
    const float* ur, const float* ui, const float* ubr, const float* ubi,
    float* __restrict__ out, unsigned* flags)
{
    float* hbuf  = (float*)(dsm + SM_HBUF);
    float* stage = (float*)(dsm + SM_STAGE);
    float* ring  = (float*)(dsm + SM_RING);
    const unsigned hb = su32(hbuf), st = su32(stage), mb = su32(dsm + SM_MBAR);
    const unsigned rg = su32(ring);

    const int tid = threadIdx.x, lane = tid & 31;
    const int jg = tid >> 4, kg = tid & 15;
    const int j0 = (int)rank * 64 + jg * 4, jj = j0 & 255;
    const bool jhi = j0 >= 256;

    unsigned dsth, dstm;
    { const int d = tid & 7;
      asm("mapa.shared::cluster.u32 %0, %1, %2;" : "=r"(dsth) : "r"(hb), "r"(d));
      asm("mapa.shared::cluster.u32 %0, %1, %2;" : "=r"(dstm) : "r"(mb), "r"(d)); }
    const unsigned dslot = dsth + (unsigned)(rank * 256);

    unsigned long long w2[4][16];
    load_u(w2, kg, jj, jhi, ur, ui);
    const float4 ub = jhi ? *(const float4*)(ubi + jj) : *(const float4*)(ubr + jj);

    const float* wx_b = wx + (size_t)b * (T_LEN * HD);
    float* out_b = out + (size_t)b * (T_LEN * HD);
    const float* wx_cta = wx_b + rank * 64;
    const unsigned* my_flag = flags + b * 8 + rank;

    if (tid < 16) {
        while (ld_acq(my_flag) < 1u) __nanosleep(256);
#pragma unroll
        for (int s = 0; s < PD; ++s) {
            cp16(rg + (unsigned)(s * 256 + tid * 16), wx_cta + (size_t)s * HD + tid * 4);
            asm volatile("cp.async.commit_group;" ::: "memory");
        }
    }
    if (tid < 32) asm volatile("cp.async.wait_group 3;" ::: "memory");
    __syncthreads();

    const bool sl = ((lane & 15) == 0), ol = ((lane & 15) == 8);

    // t = 0
    {
        float4 wv = *(const float4*)&ring[jg * 4];
        wv.x += ub.x; wv.y += ub.y; wv.z += ub.z; wv.w += ub.w;
        if (sl | ol) {
            float4 y;
            y.x = hw_tanh(wv.x); y.y = hw_tanh(wv.y);
            y.z = hw_tanh(wv.z); y.w = hw_tanh(wv.w);
            if (sl) *(float4*)&stage[jg * 4] = y;
            else    *(float4*)(out_b + j0) = y;
        }
        if (tid < 16) {
            cp16(rg + (unsigned)((PD & 7) * 256 + tid * 16), wx_cta + (size_t)PD * HD + tid * 4);
            asm volatile("cp.async.commit_group;" ::: "memory");
        }
        if (tid < 32) asm volatile("cp.async.wait_group 3;" ::: "memory");
        __syncthreads();
        if (tid < 8) bulk_send(dslot, st, dstm);
    }

    for (int t = 1; t < T_LEN; ++t) {
        const int tp = t + PD;
        if (tid < 16 && tp < T_LEN) {
            if ((tp & 15) == 0) {
                const unsigned need = (unsigned)((tp >> 4) + 1);
                while (ld_acq(my_flag) < need) __nanosleep(128);
            }
            cp16(rg + (unsigned)((tp & 7) * 256 + tid * 16), wx_cta + (size_t)tp * HD + tid * 4);
            asm volatile("cp.async.commit_group;" ::: "memory");
        }
        float4 wv = *(const float4*)&ring[(t & 7) * 64 + jg * 4];
        wv.x += ub.x; wv.y += ub.y; wv.z += ub.z; wv.w += ub.w;

        const int use = t - 1, rbuf = use & 1;
        mbar_wait(mb + rbuf * 8, (unsigned)((use >> 1) & 1));
        if (tid == 0) rearm(mb + rbuf * 8);

        unsigned long long h2[16];
        const float* hp = hbuf + rbuf * HD;
#pragma unroll
        for (int q = 0; q < 8; ++q) {
            ulonglong2 v = *(const ulonglong2*)(hp + q * 64 + kg * 4);
            h2[2*q] = v.x; h2[2*q+1] = v.y;
        }
        unsigned long long a0 = 0, a1 = 0, a2 = 0, a3 = 0;
#pragma unroll
        for (int q = 0; q < 16; ++q) {
            FMA2(a0, h2[q], w2[0][q]); FMA2(a1, h2[q], w2[1][q]);
            FMA2(a2, h2[q], w2[2][q]); FMA2(a3, h2[q], w2[3][q]);
        }
        float s0, s1, s2, s3, hq;
        unpackf2(a0, s0, hq); s0 += hq; unpackf2(a1, s1, hq); s1 += hq;
        unpackf2(a2, s2, hq); s2 += hq; unpackf2(a3, s3, hq); s3 += hq;
#pragma unroll
        for (int off = 1; off < 16; off <<= 1) {
            s0 += __shfl_xor_sync(0xffffffffu, s0, off);
            s1 += __shfl_xor_sync(0xffffffffu, s1, off);
            s2 += __shfl_xor_sync(0xffffffffu, s2, off);
            s3 += __shfl_xor_sync(0xffffffffu, s3, off);
        }
        if (sl | ol) {
            float4 y;
            y.x = hw_tanh(wv.x + s0); y.y = hw_tanh(wv.y + s1);
            y.z = hw_tanh(wv.z + s2); y.w = hw_tanh(wv.w + s3);
            if (sl) { if (t < T_LEN - 1) *(float4*)&stage[jg * 4] = y; }
            else    { *(float4*)(out_b + (size_t)t * HD + j0) = y; }
        }
        if (t < T_LEN - 1) {
            if (tid < 32) asm volatile("cp.async.wait_group 3;" ::: "memory");
            __syncthreads();
            if (tid < 8)
                bulk_send(dslot + (unsigned)((t & 1) * 2048), st, dstm + (unsigned)((t & 1) * 8));
        }
    }
}

// ---------------------------------------------------------------------------
__global__ void __cluster_dims__(8, 1, 1) __launch_bounds__(256, 1)
fused_scan(const float* __restrict__ wx0,
           const float* l0_ur, const float* l0_ui, const float* l0_ubr, const float* l0_ubi,
           const float* l1_wr, const float* l1_wi, const float* l1_wbr, const float* l1_wbi,
           const float* l1_ur, const float* l1_ui, const float* l1_ubr, const float* l1_ubi,
           float* wx1, float* out, unsigned* flags)
{
    extern __shared__ char dsm[];
    unsigned rank;
    asm("mov.u32 %0, %%cluster_ctarank;" : "=r"(rank));
    const int tid = threadIdx.x, cl = blockIdx.x >> 3;

    if (tid == 0) {
        const unsigned mb = su32(dsm + SM_MBAR);
        asm volatile("mbarrier.init.shared.b64 [%0], %1;" :: "r"(mb),     "r"(1u) : "memory");
        asm volatile("mbarrier.init.shared.b64 [%0], %1;" :: "r"(mb + 8), "r"(1u) : "memory");
        rearm(mb); rearm(mb + 8);
    }
    __syncthreads();
    asm volatile("barrier.cluster.arrive.aligned;" ::: "memory");
    asm volatile("barrier.cluster.wait.aligned;"   ::: "memory");

    if (cl < 8)
        scan_l0(dsm, rank, cl, wx0, l0_ur, l0_ui, l0_ubr, l0_ubi,
                l1_wr, l1_wi, l1_wbr, l1_wbi, wx1, flags);
    else
        scan_l1(dsm, rank, cl - 8, wx1, l1_ur, l1_ui, l1_ubr, l1_ubi, out, flags);

    asm volatile("barrier.cluster.arrive;" ::: "memory");
    asm volatile("barrier.cluster.wait;"   ::: "memory");
}

// ---------------------------------------------------------------------------
extern "C" void kernel_launch(void* const* d_in, const int* in_sizes, int n_in,
                              void* d_out, int out_size)
{
    const float* x      = (const float*)d_in[0];
    const float* l0_wr  = (const float*)d_in[1];
    const float* l0_wi  = (const float*)d_in[2];
    const float* l0_wbr = (const float*)d_in[3];
    const float* l0_wbi = (const float*)d_in[4];
    const float* l0_ur  = (const float*)d_in[5];
    const float* l0_ui  = (const float*)d_in[6];
    const float* l0_ubr = (const float*)d_in[7];
    const float* l0_ubi = (const float*)d_in[8];
    const float* l1_wr  = (const float*)d_in[9];
    const float* l1_wi  = (const float*)d_in[10];
    const float* l1_wbr = (const float*)d_in[11];
    const float* l1_wbi = (const float*)d_in[12];
    const float* l1_ur  = (const float*)d_in[13];
    const float* l1_ui  = (const float*)d_in[14];
    const float* l1_ubr = (const float*)d_in[15];
    const float* l1_ubi = (const float*)d_in[16];

    float* out = (float*)d_out;

    void *p_wx_v = nullptr, *p_wx1_v = nullptr, *p_fl_v = nullptr;
    cudaGetSymbolAddress(&p_wx_v,  g_wx);
    cudaGetSymbolAddress(&p_wx1_v, g_wx1);
    cudaGetSymbolAddress(&p_fl_v,  g_flags);
    float* p_wx  = (float*)p_wx_v;
    float* p_wx1 = (float*)p_wx1_v;
    unsigned* p_fl = (unsigned*)p_fl_v;

    cudaFuncSetAttribute(fused_scan,
                         cudaFuncAttributeMaxDynamicSharedMemorySize, SMEM_TOTAL);
    cudaMemsetAsync(p_fl, 0, sizeof(unsigned) * 64);

    dim3 pgrid(NROWS / 128, HD / 128);
    proj_kernel<<<pgrid, 256>>>(x, l0_wr, l0_wi, l0_wbr, l0_wbi, p_wx);

    fused_scan<<<128, 256, SMEM_TOTAL>>>(p_wx,
                                         l0_ur, l0_ui, l0_ubr, l0_ubi,
                                         l1_wr, l1_wi, l1_wbr, l1_wbi,
                                         l1_ur, l1_ui, l1_ubr, l1_ubi,
                                         p_wx1, out, p_fl);
}